// round 1
// baseline (speedup 1.0000x reference)
#include <cuda_runtime.h>

#define FULLM 0xffffffffu

namespace {
constexpr int NOUT = 32;
constexpr int KTOT = 288;   // 3*3*32
constexpr int BTOT = 576;   // 16*6*6
constexpr float EPSF = 1e-9f;
constexpr float LOG2PI = 1.8378770664093453f;
}

struct Smem {
    float pose[KTOT][16];   // im2col'd pose tile for this b
    float act[KTOT];        // activations
    float acc[NOUT][33];    // cross-warp reduction: S1[16], S2[16], rsum
    float mu[NOUT][17];     // padded to kill bank conflicts
    float is[NOUT][17];     // 0.5 / sigma2
    float L0[NOUT];         // log(a_out+eps) - 0.5*sum_d log(2pi sigma2)
    float a[NOUT];          // a_out
};

template<int PASS>
__device__ __forceinline__ void do_pass(Smem& s, const float* __restrict__ w,
                                        int tid, float inv_temp,
                                        float bv, float ba)
{
    const int warp = tid >> 5;
    const int o = tid & 31;

    // zero the reduction buffer
    for (int idx = tid; idx < NOUT * 33; idx += 256)
        (&s.acc[0][0])[idx] = 0.f;
    __syncthreads();

    float mu_r[16], is_r[16], L0_r = 0.f;
    if (PASS > 0) {
        #pragma unroll
        for (int d = 0; d < 16; d++) { mu_r[d] = s.mu[o][d]; is_r[d] = s.is[o][d]; }
        L0_r = s.L0[o];
    }

    float S1[16], S2[16];
    #pragma unroll
    for (int d = 0; d < 16; d++) { S1[d] = 0.f; S2[d] = 0.f; }
    float rsum = 0.f;

    for (int k = warp; k < KTOT; k += 8) {
        // each lane loads w[k, o, :, :] (16 floats, coalesced across lanes)
        const float4* wp = reinterpret_cast<const float4*>(w + (k * 32 + o) * 16);
        float4 wa = wp[0], wb = wp[1], wc = wp[2], wd = wp[3];
        float wr[16] = {wa.x, wa.y, wa.z, wa.w, wb.x, wb.y, wb.z, wb.w,
                        wc.x, wc.y, wc.z, wc.w, wd.x, wd.y, wd.z, wd.w};

        // vote v[m*4+n] = sum_c pose[m*4+c] * w[c*4+n]   (pose via LDS broadcast)
        float v[16];
        #pragma unroll
        for (int m = 0; m < 4; m++) {
            float p0 = s.pose[k][m * 4 + 0];
            float p1 = s.pose[k][m * 4 + 1];
            float p2 = s.pose[k][m * 4 + 2];
            float p3 = s.pose[k][m * 4 + 3];
            #pragma unroll
            for (int nn = 0; nn < 4; nn++) {
                v[m * 4 + nn] = fmaf(p0, wr[nn],
                                fmaf(p1, wr[4 + nn],
                                fmaf(p2, wr[8 + nn], p3 * wr[12 + nn])));
            }
        }

        float rw;
        if (PASS == 0) {
            rw = s.act[k] * (1.f / 32.f);          // uniform r = 1/O
        } else {
            // E-step: logit = log(a+eps) - 0.5*(sum log(2pi s2) + sum diff2/s2)
            float accd = 0.f;
            #pragma unroll
            for (int d = 0; d < 16; d++) {
                float df = v[d] - mu_r[d];
                accd = fmaf(df * df, is_r[d], accd);
            }
            float logit = L0_r - accd;
            // softmax over O = 32 lanes of the warp
            float mx = logit;
            #pragma unroll
            for (int off = 16; off > 0; off >>= 1)
                mx = fmaxf(mx, __shfl_xor_sync(FULLM, mx, off));
            float e = __expf(logit - mx);
            float ssum = e;
            #pragma unroll
            for (int off = 16; off > 0; off >>= 1)
                ssum += __shfl_xor_sync(FULLM, ssum, off);
            rw = (e / ssum) * s.act[k];
        }

        rsum += rw;
        #pragma unroll
        for (int d = 0; d < 16; d++) {
            float t = rw * v[d];
            S1[d] += t;
            S2[d] = fmaf(t, v[d], S2[d]);
        }
    }

    // cross-warp reduction (conflict-free: stride 33 is odd)
    #pragma unroll
    for (int d = 0; d < 16; d++) atomicAdd(&s.acc[o][d], S1[d]);
    #pragma unroll
    for (int d = 0; d < 16; d++) atomicAdd(&s.acc[o][16 + d], S2[d]);
    atomicAdd(&s.acc[o][32], rsum);
    __syncthreads();

    // M-step epilogue: warp 0, lane = o
    if (tid < 32) {
        float rs = s.acc[o][32] + EPSF;
        float irs = 1.f / rs;
        float logsum = 0.f;
        #pragma unroll
        for (int d = 0; d < 16; d++) {
            float mu = s.acc[o][d] * irs;
            float sg = fmaxf(s.acc[o][16 + d] * irs - mu * mu, 0.f) + EPSF;
            s.mu[o][d] = mu;
            s.is[o][d] = 0.5f / sg;
            logsum += __logf(sg);
        }
        float costsum = (16.f * bv + 0.5f * logsum) * rs;
        float x = inv_temp * (ba - costsum);
        float a = 1.f / (1.f + __expf(-x));
        s.a[o] = a;
        s.L0[o] = __logf(a + EPSF) - 0.5f * (16.f * LOG2PI + logsum);
    }
    __syncthreads();
}

__global__ void __launch_bounds__(256, 2)
convcaps_kernel(const float* __restrict__ pose,
                const float* __restrict__ act,
                const float* __restrict__ w,
                const float* __restrict__ beta_v,
                const float* __restrict__ beta_a,
                float* __restrict__ out)
{
    __shared__ Smem s;
    const int b = blockIdx.x;
    const int n = b / 36, rem = b % 36;
    const int ph = rem / 6, pw = rem % 6;
    const int h0 = ph * 2, w0c = pw * 2;
    const int tid = threadIdx.x;

    // im2col load of the 3x3x32 capsule neighborhood (poses + activations)
    for (int idx = tid; idx < KTOT * 16; idx += 256) {
        int k = idx >> 4, d = idx & 15;
        int ki = k / 96, kj = (k >> 5) % 3, c = k & 31;
        s.pose[k][d] =
            pose[(((n * 14 + h0 + ki) * 14 + (w0c + kj)) * 32 + c) * 16 + d];
    }
    for (int k = tid; k < KTOT; k += 256) {
        int ki = k / 96, kj = (k >> 5) % 3, c = k & 31;
        s.act[k] = act[((n * 14 + h0 + ki) * 14 + (w0c + kj)) * 32 + c];
    }

    const int o = tid & 31;
    const float bv = beta_v[o];
    const float ba = beta_a[o];

    // 3 fused passes: M0, E0+M1, E1+M2   (inv_temp = 0.01*(1-0.95^(it+1)))
    do_pass<0>(s, w, tid, 0.0005f,     bv, ba);
    do_pass<1>(s, w, tid, 0.000975f,   bv, ba);
    do_pass<2>(s, w, tid, 0.00142625f, bv, ba);

    // outputs: pose (B,O,16) then activation (B,O)
    for (int idx = tid; idx < NOUT * 16; idx += 256)
        out[b * 512 + idx] = s.mu[idx >> 4][idx & 15];
    if (tid < 32)
        out[BTOT * 512 + b * 32 + tid] = s.a[tid];
}

extern "C" void kernel_launch(void* const* d_in, const int* in_sizes, int n_in,
                              void* d_out, int out_size) {
    const float* pose = (const float*)d_in[0];
    const float* act  = (const float*)d_in[1];
    const float* w    = (const float*)d_in[2];
    const float* bv   = (const float*)d_in[3];
    const float* ba   = (const float*)d_in[4];
    convcaps_kernel<<<BTOT, 256>>>(pose, act, w, bv, ba, (float*)d_out);
}